// round 1
// baseline (speedup 1.0000x reference)
#include <cuda_runtime.h>
#include <math.h>
#include <float.h>

// Problem constants (fixed shapes)
#define V_   8000
#define D_   300
#define B_   128
#define L_   300
#define NG   3            // NGRAM
#define KW   (2*NG+1)     // 7 window taps
#define C_   54
#define DC   64           // D-chunk width for the message-passing kernel
#define NCHUNK ((D_ + DC - 1) / DC)   // 5

// Scratch (device globals; no allocations allowed)
__device__ float g_w[B_ * L_ * KW];   // per-doc edge weights  (1.05 MB)
__device__ float g_x[B_ * D_];        // relu(pooled)          (150 KB)
__device__ float g_s[D_];             // BN scale
__device__ float g_t[D_];             // BN shift

// ---------------------------------------------------------------------------
// Kernel 0: gather edge weights  w[b,l,k] = edge_w[edges_matrix[doc[l], doc[clip(l+k-3)]]]
// ---------------------------------------------------------------------------
__global__ void edgew_kernel(const int* __restrict__ docs,
                             const int* __restrict__ edges_matrix,
                             const float* __restrict__ edge_w) {
    __shared__ int tokS[L_];
    int b = blockIdx.x;
    for (int l = threadIdx.x; l < L_; l += blockDim.x)
        tokS[l] = docs[b * L_ + l];
    __syncthreads();
    for (int i = threadIdx.x; i < L_ * KW; i += blockDim.x) {
        int l = i / KW, k = i - l * KW;
        int nbr = l - NG + k;
        nbr = nbr < 0 ? 0 : (nbr > L_ - 1 ? L_ - 1 : nbr);
        long long eid = edges_matrix[(long long)tokS[l] * V_ + tokS[nbr]];
        g_w[b * (L_ * KW) + i] = edge_w[eid];
    }
}

// ---------------------------------------------------------------------------
// Kernel 1: 2-step message passing for one (doc, D-chunk); fused pool + ReLU.
// Dynamic smem: hA[300*64] hB[300*64] wS[2100] etaS[300] (floats) + tokS[300] ints
// ---------------------------------------------------------------------------
__global__ void mp_kernel(const float* __restrict__ node_embed,
                          const float* __restrict__ node_eta,
                          const int* __restrict__ docs) {
    extern __shared__ float sm[];
    float* hA   = sm;                 // 19200
    float* hB   = hA + L_ * DC;       // 19200
    float* wS   = hB + L_ * DC;       // 2100
    float* etaS = wS + L_ * KW;       // 300
    int*   tokS = (int*)(etaS + L_);  // 300

    const int b  = blockIdx.y;
    const int d0 = blockIdx.x * DC;
    const int Dc = (D_ - d0) < DC ? (D_ - d0) : DC;
    const int tid = threadIdx.x;
    const int nthr = blockDim.x;

    // tokens + eta
    for (int l = tid; l < L_; l += nthr) {
        int t = docs[b * L_ + l];
        tokS[l] = t;
        etaS[l] = node_eta[t];
    }
    // edge weights (coalesced from scratch)
    for (int i = tid; i < L_ * KW; i += nthr)
        wS[i] = g_w[b * (L_ * KW) + i];
    __syncthreads();

    // h init = node_embed[doc[l], d0+d]; pad columns with 0
    for (int e = tid; e < L_ * DC; e += nthr) {
        int l = e >> 6, d = e & (DC - 1);
        hA[e] = (d < Dc) ? node_embed[(long long)tokS[l] * D_ + d0 + d] : 0.f;
    }
    __syncthreads();

    float* cur = hA;
    float* nxt = hB;
    #pragma unroll
    for (int step = 0; step < 2; step++) {
        for (int e = tid; e < L_ * DC; e += nthr) {
            int l = e >> 6;
            float msg = -FLT_MAX;
            const float* wrow = &wS[l * KW];
            #pragma unroll
            for (int k = 0; k < KW; k++) {
                int nbr = l - NG + k;
                if (nbr >= 0 && nbr < L_)
                    msg = fmaxf(msg, wrow[k] * cur[e + (k - NG) * DC]);
            }
            float eta = etaS[l];
            nxt[e] = eta * cur[e] + (1.f - eta) * msg;
        }
        __syncthreads();
        float* tmp = cur; cur = nxt; nxt = tmp;
    }

    // pooled sum over l, ReLU, write x[b, d0+d]
    // 256 threads: d = tid&63, part = tid>>6 (4 partial sums per column)
    int d = tid & (DC - 1), part = tid >> 6;
    float s = 0.f;
    for (int l = part; l < L_; l += 4)
        s += cur[l * DC + d];
    nxt[part * DC + d] = s;   // reuse the other buffer for the reduction
    __syncthreads();
    if (part == 0 && d < Dc) {
        float tot = nxt[d] + nxt[DC + d] + nxt[2 * DC + d] + nxt[3 * DC + d];
        g_x[b * D_ + d0 + d] = fmaxf(tot, 0.f);
    }
}

// ---------------------------------------------------------------------------
// Kernel 2: per-feature BN stats over batch (two-pass), folded into scale/shift
// ---------------------------------------------------------------------------
__global__ void bn_kernel(const float* __restrict__ gamma,
                          const float* __restrict__ beta) {
    int d = blockIdx.x * blockDim.x + threadIdx.x;
    if (d >= D_) return;
    float sum = 0.f;
    for (int b = 0; b < B_; b++) sum += g_x[b * D_ + d];
    float mean = sum * (1.f / B_);
    float var = 0.f;
    for (int b = 0; b < B_; b++) {
        float v = g_x[b * D_ + d] - mean;
        var += v * v;
    }
    var *= (1.f / B_);
    float sc = gamma[d] * rsqrtf(var + 1e-5f);
    g_s[d] = sc;
    g_t[d] = beta[d] - mean * sc;
}

// ---------------------------------------------------------------------------
// Kernel 3: x_norm @ W + b -> sigmoid.  One block per batch row.
// ---------------------------------------------------------------------------
__global__ void out_kernel(const float* __restrict__ W,
                           const float* __restrict__ bias,
                           float* __restrict__ out) {
    __shared__ float xs[D_];
    int b = blockIdx.x;
    for (int d = threadIdx.x; d < D_; d += blockDim.x)
        xs[d] = g_x[b * D_ + d] * g_s[d] + g_t[d];
    __syncthreads();
    int c = threadIdx.x;
    if (c < C_) {
        float acc = bias[c];
        #pragma unroll 4
        for (int d = 0; d < D_; d++)
            acc = fmaf(xs[d], W[d * C_ + c], acc);
        out[b * C_ + c] = 1.f / (1.f + expf(-acc));
    }
}

// ---------------------------------------------------------------------------
extern "C" void kernel_launch(void* const* d_in, const int* in_sizes, int n_in,
                              void* d_out, int out_size) {
    const float* node_embed   = (const float*)d_in[0];
    const float* node_eta     = (const float*)d_in[1];
    const float* edge_w       = (const float*)d_in[2];
    const float* bn_gamma     = (const float*)d_in[3];
    const float* bn_beta      = (const float*)d_in[4];
    const float* Wmat         = (const float*)d_in[5];
    const float* bias         = (const float*)d_in[6];
    const int*   docs         = (const int*)d_in[7];
    const int*   edges_matrix = (const int*)d_in[8];
    float* out = (float*)d_out;

    // mp_kernel dynamic smem: (19200+19200+2100+300)*4 + 300*4 bytes
    const int smemBytes = (L_ * DC * 2 + L_ * KW + L_) * (int)sizeof(float)
                        + L_ * (int)sizeof(int);
    static bool attr_set = false;   // idempotent host-side attribute, safe under capture
    cudaFuncSetAttribute(mp_kernel, cudaFuncAttributeMaxDynamicSharedMemorySize, smemBytes);

    edgew_kernel<<<B_, 256>>>(docs, edges_matrix, edge_w);

    dim3 grid(NCHUNK, B_);
    mp_kernel<<<grid, 256, smemBytes>>>(node_embed, node_eta, docs);

    bn_kernel<<<(D_ + 127) / 128, 128>>>(bn_gamma, bn_beta);

    out_kernel<<<B_, 64>>>(Wmat, bias, out);

    (void)attr_set; (void)in_sizes; (void)n_in; (void)out_size;
}

// round 2
// speedup vs baseline: 2.6619x; 2.6619x over previous
#include <cuda_runtime.h>
#include <math.h>
#include <float.h>

// Problem constants (fixed shapes)
#define V_   8000
#define D_   300
#define B_   128
#define L_   300
#define NG   3            // NGRAM
#define KW   (2*NG+1)     // 7 window taps
#define C_   54
#define DC   32           // D-chunk width for the message-passing kernel
#define NCHUNK ((D_ + DC - 1) / DC)   // 10
#define NSEG 8            // row segments per block in mp

// Scratch (device globals; no allocations allowed)
__device__ float g_w[B_ * L_ * KW];   // per-doc edge weights  (1.05 MB)
__device__ float g_x[B_ * D_];        // relu(pooled)          (150 KB)
__device__ float g_s[D_];             // BN scale
__device__ float g_t[D_];             // BN shift

// ---------------------------------------------------------------------------
// Kernel 0: gather edge weights  w[b,l,k] = edge_w[edges_matrix[doc[l], doc[clip(l+k-3)]]]
// ---------------------------------------------------------------------------
__global__ void edgew_kernel(const int* __restrict__ docs,
                             const int* __restrict__ edges_matrix,
                             const float* __restrict__ edge_w) {
    __shared__ int tokS[L_];
    int b = blockIdx.x;
    for (int l = threadIdx.x; l < L_; l += blockDim.x)
        tokS[l] = docs[b * L_ + l];
    __syncthreads();
    for (int i = threadIdx.x; i < L_ * KW; i += blockDim.x) {
        int l = i / KW, k = i - l * KW;
        int nbr = l - NG + k;
        nbr = nbr < 0 ? 0 : (nbr > L_ - 1 ? L_ - 1 : nbr);
        long long eid = edges_matrix[(long long)tokS[l] * V_ + tokS[nbr]];
        g_w[b * (L_ * KW) + i] = edge_w[eid];
    }
}

// ---------------------------------------------------------------------------
// Kernel 1: 2-step message passing for one (doc, 32-wide D-chunk).
// Register sliding window over l; fused pool + ReLU.
// smem: hA[300*32] hB[300*32] wS[2100] etaS[300] floats + tokS[300] ints = 87.6 KB
// -> 2 blocks/SM.
// ---------------------------------------------------------------------------
__global__ void __launch_bounds__(256, 2)
mp_kernel(const float* __restrict__ node_embed,
          const float* __restrict__ node_eta,
          const int* __restrict__ docs) {
    extern __shared__ float sm[];
    float* hA   = sm;                 // 9600
    float* hB   = hA + L_ * DC;       // 9600
    float* wS   = hB + L_ * DC;       // 2100
    float* etaS = wS + L_ * KW;       // 300
    int*   tokS = (int*)(etaS + L_);  // 300

    const int b  = blockIdx.y;
    const int d0 = blockIdx.x * DC;
    const int Dc = (D_ - d0) < DC ? (D_ - d0) : DC;
    const int tid = threadIdx.x;

    // tokens + eta
    for (int l = tid; l < L_; l += 256) {
        int t = docs[b * L_ + l];
        tokS[l] = t;
        etaS[l] = node_eta[t];
    }
    // edge weights (coalesced from scratch)
    for (int i = tid; i < L_ * KW; i += 256)
        wS[i] = g_w[b * (L_ * KW) + i];
    __syncthreads();

    // h init = node_embed[doc[l], d0+d]; pad columns with 0
    for (int e = tid; e < L_ * DC; e += 256) {
        int l = e >> 5, d = e & (DC - 1);
        hA[e] = (d < Dc) ? node_embed[(long long)tokS[l] * D_ + d0 + d] : 0.f;
    }
    __syncthreads();

    // Each thread owns column d within row segment [ls, le)
    const int d   = tid & (DC - 1);
    const int seg = tid >> 5;                 // 0..7
    const int ls  = (seg * L_) / NSEG;
    const int le  = ((seg + 1) * L_) / NSEG;

    float* cur = hA;
    float* nxt = hB;
    #pragma unroll
    for (int step = 0; step < 2; step++) {
        // register window: win[j] = cur[(l-3+j)*DC + d]
        float win[KW];
        #pragma unroll
        for (int j = 0; j < KW; j++) {
            int r = ls - NG + j;
            win[j] = (r >= 0 && r < L_) ? cur[r * DC + d] : 0.f;
        }
        for (int l = ls; l < le; l++) {
            const float* wrow = &wS[l * KW];  // broadcast across the 32 d-lanes
            float msg = -FLT_MAX;
            #pragma unroll
            for (int k = 0; k < KW; k++) {
                int nbr = l - NG + k;
                if (nbr >= 0 && nbr < L_)
                    msg = fmaxf(msg, wrow[k] * win[k]);
            }
            float eta = etaS[l];
            nxt[l * DC + d] = eta * win[NG] + (1.f - eta) * msg;
            #pragma unroll
            for (int j = 0; j < KW - 1; j++) win[j] = win[j + 1];
            int r = l + 1 + NG;
            win[KW - 1] = (r < L_) ? cur[r * DC + d] : 0.f;
        }
        __syncthreads();
        float* tmp = cur; cur = nxt; nxt = tmp;
    }

    // pooled sum over l, ReLU, write x[b, d0+d] (8 partials per column)
    float s = 0.f;
    for (int l = seg; l < L_; l += NSEG)
        s += cur[l * DC + d];
    nxt[seg * DC + d] = s;                    // reuse other buffer
    __syncthreads();
    if (seg == 0 && d < Dc) {
        float tot = 0.f;
        #pragma unroll
        for (int p = 0; p < NSEG; p++) tot += nxt[p * DC + d];
        g_x[b * D_ + d0 + d] = fmaxf(tot, 0.f);
    }
}

// ---------------------------------------------------------------------------
// Kernel 2: BN stats — one block per feature d, one thread per batch row.
// Single pass sum + sumsq, warp-shuffle reduce.
// ---------------------------------------------------------------------------
__global__ void bn_kernel(const float* __restrict__ gamma,
                          const float* __restrict__ beta) {
    __shared__ float s1[4], s2[4];
    int d = blockIdx.x;
    int tid = threadIdx.x;            // 0..127 == batch row
    float v = g_x[tid * D_ + d];
    float a = v, q = v * v;
    #pragma unroll
    for (int o = 16; o > 0; o >>= 1) {
        a += __shfl_down_sync(0xffffffffu, a, o);
        q += __shfl_down_sync(0xffffffffu, q, o);
    }
    if ((tid & 31) == 0) { s1[tid >> 5] = a; s2[tid >> 5] = q; }
    __syncthreads();
    if (tid == 0) {
        float sum = s1[0] + s1[1] + s1[2] + s1[3];
        float sq  = s2[0] + s2[1] + s2[2] + s2[3];
        float mean = sum * (1.f / B_);
        float var  = sq * (1.f / B_) - mean * mean;
        float sc = gamma[d] * rsqrtf(var + 1e-5f);
        g_s[d] = sc;
        g_t[d] = beta[d] - mean * sc;
    }
}

// ---------------------------------------------------------------------------
// Kernel 3: sigmoid(x_norm @ W + b). One block per batch row;
// 432 threads = 54 outputs x 8 d-partitions; smem reduce.
// ---------------------------------------------------------------------------
__global__ void out_kernel(const float* __restrict__ W,
                           const float* __restrict__ bias,
                           float* __restrict__ out) {
    __shared__ float xs[D_];
    __shared__ float red[8][C_];
    int b = blockIdx.x;
    int tid = threadIdx.x;
    for (int dd = tid; dd < D_; dd += blockDim.x)
        xs[dd] = g_x[b * D_ + dd] * g_s[dd] + g_t[dd];
    __syncthreads();
    int c = tid % C_, part = tid / C_;  // part 0..7
    float acc = 0.f;
    for (int dd = part; dd < D_; dd += 8)
        acc = fmaf(xs[dd], W[dd * C_ + c], acc);
    red[part][c] = acc;
    __syncthreads();
    if (part == 0) {
        float tot = bias[c];
        #pragma unroll
        for (int p = 0; p < 8; p++) tot += red[p][c];
        out[b * C_ + c] = 1.f / (1.f + expf(-tot));
    }
}

// ---------------------------------------------------------------------------
extern "C" void kernel_launch(void* const* d_in, const int* in_sizes, int n_in,
                              void* d_out, int out_size) {
    const float* node_embed   = (const float*)d_in[0];
    const float* node_eta     = (const float*)d_in[1];
    const float* edge_w       = (const float*)d_in[2];
    const float* bn_gamma     = (const float*)d_in[3];
    const float* bn_beta      = (const float*)d_in[4];
    const float* Wmat         = (const float*)d_in[5];
    const float* bias         = (const float*)d_in[6];
    const int*   docs         = (const int*)d_in[7];
    const int*   edges_matrix = (const int*)d_in[8];
    float* out = (float*)d_out;

    const int smemBytes = (L_ * DC * 2 + L_ * KW + L_) * (int)sizeof(float)
                        + L_ * (int)sizeof(int);   // 87600 B
    cudaFuncSetAttribute(mp_kernel, cudaFuncAttributeMaxDynamicSharedMemorySize, smemBytes);

    edgew_kernel<<<B_, 512>>>(docs, edges_matrix, edge_w);

    dim3 grid(NCHUNK, B_);
    mp_kernel<<<grid, 256, smemBytes>>>(node_embed, node_eta, docs);

    bn_kernel<<<D_, B_>>>(bn_gamma, bn_beta);

    out_kernel<<<B_, 8 * C_>>>(Wmat, bias, out);

    (void)in_sizes; (void)n_in; (void)out_size;
}

// round 3
// speedup vs baseline: 3.9909x; 1.4992x over previous
#include <cuda_runtime.h>
#include <math.h>
#include <float.h>

// Problem constants (fixed shapes)
#define V_   8000
#define D_   300
#define B_   128
#define L_   300
#define NG   3             // NGRAM
#define KW   (2*NG+1)      // 7 window taps
#define WP   8             // padded tap row: w0..w6, eta
#define C_   54
#define DC   32            // D-chunk width
#define NCHUNK ((D_ + DC - 1) / DC)   // 10
#define NSEG 12            // row segments per block (384 threads)
#define SEGL (L_ / NSEG)   // 25
#define HR   (L_ + 8)      // padded h rows: 3 halo top, 5 halo bottom

// Scratch (device globals; no allocations allowed)
__device__ float g_w[B_ * L_ * WP];   // per-doc [w0..w6, eta] rows (1.23 MB)
__device__ float g_x[B_ * D_];        // relu(pooled)
__device__ float g_s[D_];             // BN scale
__device__ float g_t[D_];             // BN shift

// ---------------------------------------------------------------------------
// Kernel 0: gather edge weights + eta into padded rows.
// g_w[b][l][k] = edge_w[edges_matrix[doc[l], doc[l+k-3]]] for valid taps,
//               1.0f for invalid taps (pairs with -FLT_MAX halo in mp),
// g_w[b][l][7] = node_eta[doc[l]].
// ---------------------------------------------------------------------------
__global__ void edgew_kernel(const int* __restrict__ docs,
                             const int* __restrict__ edges_matrix,
                             const float* __restrict__ edge_w,
                             const float* __restrict__ node_eta) {
    __shared__ int tokS[L_];
    int b = blockIdx.x;
    for (int l = threadIdx.x; l < L_; l += blockDim.x)
        tokS[l] = docs[b * L_ + l];
    __syncthreads();
    for (int i = threadIdx.x; i < L_ * WP; i += blockDim.x) {
        int l = i >> 3, k = i & 7;
        float v;
        if (k == 7) {
            v = node_eta[tokS[l]];
        } else {
            int nbr = l - NG + k;
            if (nbr < 0 || nbr >= L_) {
                v = 1.0f;
            } else {
                long long eid = edges_matrix[(long long)tokS[l] * V_ + tokS[nbr]];
                v = edge_w[eid];
            }
        }
        g_w[b * (L_ * WP) + i] = v;
    }
}

// ---------------------------------------------------------------------------
// Kernel 1: 2-step message passing for one (doc, 32-wide D-chunk).
// Branch-free inner loop: halo rows pinned to -FLT_MAX, invalid w == 1.0.
// smem: hA[308*32] hB[308*32] wS[300*8] floats + tokS[300] ints ~= 89.6 KB
// -> 2 blocks/SM.
// ---------------------------------------------------------------------------
__global__ void __launch_bounds__(384, 2)
mp_kernel(const float* __restrict__ node_embed,
          const int* __restrict__ docs) {
    extern __shared__ float sm[];
    float* hA  = sm;                   // HR*32 = 9856
    float* hB  = hA + HR * DC;         // 9856
    float* wS  = hB + HR * DC;         // 2400 (16B-aligned: 2*9856*4 % 16 == 0)
    int*  tokS = (int*)(wS + L_ * WP); // 300

    const int b  = blockIdx.y;
    const int d0 = blockIdx.x * DC;
    const int Dc = (D_ - d0) < DC ? (D_ - d0) : DC;
    const int tid = threadIdx.x;

    // tokens
    for (int l = tid; l < L_; l += 384)
        tokS[l] = docs[b * L_ + l];
    // packed w/eta rows (coalesced)
    for (int i = tid; i < L_ * WP; i += 384)
        wS[i] = g_w[b * (L_ * WP) + i];
    // halo rows -FLT_MAX in both buffers: rows [0,3) and [303,308)
    for (int i = tid; i < 3 * DC; i += 384) { hA[i] = -FLT_MAX; hB[i] = -FLT_MAX; }
    for (int i = tid; i < 5 * DC; i += 384) {
        hA[303 * DC + i] = -FLT_MAX; hB[303 * DC + i] = -FLT_MAX;
    }
    __syncthreads();

    // h init: padded row l+3 holds h(l); pad d-columns with 0
    for (int e = tid; e < L_ * DC; e += 384) {
        int l = e >> 5, d = e & (DC - 1);
        hA[3 * DC + e] = (d < Dc) ? node_embed[(long long)tokS[l] * D_ + d0 + d] : 0.f;
    }
    __syncthreads();

    // Thread owns column d within rows [ls, ls+25)
    const int d  = tid & (DC - 1);
    const int seg = tid >> 5;          // 0..11
    const int ls  = seg * SEGL;

    float* cur = hA;
    float* nxt = hB;
    #pragma unroll
    for (int step = 0; step < 2; step++) {
        // window regs: taps for row l live at padded rows l..l+6
        float w0 = cur[(ls + 0) * DC + d];
        float w1 = cur[(ls + 1) * DC + d];
        float w2 = cur[(ls + 2) * DC + d];
        float w3 = cur[(ls + 3) * DC + d];
        float w4 = cur[(ls + 4) * DC + d];
        float w5 = cur[(ls + 5) * DC + d];
        float w6 = cur[(ls + 6) * DC + d];
        #pragma unroll
        for (int j = 0; j < SEGL; j++) {
            int l = ls + j;
            float4 wa = *(const float4*)&wS[l * WP];
            float4 wb = *(const float4*)&wS[l * WP + 4];
            float m = fmaxf(fmaxf(fmaxf(wa.x * w0, wa.y * w1),
                                  fmaxf(wa.z * w2, wa.w * w3)),
                            fmaxf(fmaxf(wb.x * w4, wb.y * w5), wb.z * w6));
            // eta*h + (1-eta)*m == m + eta*(h - m)
            nxt[(l + 3) * DC + d] = fmaf(wb.w, w3 - m, m);
            w0 = w1; w1 = w2; w2 = w3; w3 = w4; w4 = w5; w5 = w6;
            w6 = cur[(l + 7) * DC + d];
        }
        __syncthreads();
        float* tmp = cur; cur = nxt; nxt = tmp;
    }

    // pooled sum over l, ReLU, write x[b, d0+d] (12 partials per column)
    float s = 0.f;
    #pragma unroll
    for (int j = 0; j < SEGL; j++)
        s += cur[(ls + j + 3) * DC + d];
    nxt[seg * DC + d] = s;             // reuse other buffer
    __syncthreads();
    if (seg == 0 && d < Dc) {
        float tot = 0.f;
        #pragma unroll
        for (int p = 0; p < NSEG; p++) tot += nxt[p * DC + d];
        g_x[b * D_ + d0 + d] = fmaxf(tot, 0.f);
    }
}

// ---------------------------------------------------------------------------
// Kernel 2: BN stats — one block per feature d, one thread per batch row.
// ---------------------------------------------------------------------------
__global__ void bn_kernel(const float* __restrict__ gamma,
                          const float* __restrict__ beta) {
    __shared__ float s1[4], s2[4];
    int d = blockIdx.x;
    int tid = threadIdx.x;             // 0..127 == batch row
    float v = g_x[tid * D_ + d];
    float a = v, q = v * v;
    #pragma unroll
    for (int o = 16; o > 0; o >>= 1) {
        a += __shfl_down_sync(0xffffffffu, a, o);
        q += __shfl_down_sync(0xffffffffu, q, o);
    }
    if ((tid & 31) == 0) { s1[tid >> 5] = a; s2[tid >> 5] = q; }
    __syncthreads();
    if (tid == 0) {
        float sum = s1[0] + s1[1] + s1[2] + s1[3];
        float sq  = s2[0] + s2[1] + s2[2] + s2[3];
        float mean = sum * (1.f / B_);
        float var  = sq * (1.f / B_) - mean * mean;
        float sc = gamma[d] * rsqrtf(var + 1e-5f);
        g_s[d] = sc;
        g_t[d] = beta[d] - mean * sc;
    }
}

// ---------------------------------------------------------------------------
// Kernel 3: sigmoid(x_norm @ W + b). One block per batch row; 432 threads =
// 54 outputs x 8 d-partitions; 4 independent accumulators for MLP.
// ---------------------------------------------------------------------------
__global__ void out_kernel(const float* __restrict__ W,
                           const float* __restrict__ bias,
                           float* __restrict__ out) {
    __shared__ float xs[D_];
    __shared__ float red[8][C_];
    int b = blockIdx.x;
    int tid = threadIdx.x;
    for (int dd = tid; dd < D_; dd += blockDim.x)
        xs[dd] = g_x[b * D_ + dd] * g_s[dd] + g_t[dd];
    __syncthreads();
    int c = tid % C_, part = tid / C_;  // part 0..7
    float a0 = 0.f, a1 = 0.f, a2 = 0.f, a3 = 0.f;
    #pragma unroll
    for (int dd = part; dd < D_; dd += 32) {
        a0 = fmaf(xs[dd], W[dd * C_ + c], a0);
        int d1 = dd + 8, d2 = dd + 16, d3 = dd + 24;
        if (d1 < D_) a1 = fmaf(xs[d1], W[d1 * C_ + c], a1);
        if (d2 < D_) a2 = fmaf(xs[d2], W[d2 * C_ + c], a2);
        if (d3 < D_) a3 = fmaf(xs[d3], W[d3 * C_ + c], a3);
    }
    red[part][c] = (a0 + a1) + (a2 + a3);
    __syncthreads();
    if (part == 0) {
        float tot = bias[c];
        #pragma unroll
        for (int p = 0; p < 8; p++) tot += red[p][c];
        out[b * C_ + c] = 1.f / (1.f + expf(-tot));
    }
}

// ---------------------------------------------------------------------------
extern "C" void kernel_launch(void* const* d_in, const int* in_sizes, int n_in,
                              void* d_out, int out_size) {
    const float* node_embed   = (const float*)d_in[0];
    const float* node_eta     = (const float*)d_in[1];
    const float* edge_w       = (const float*)d_in[2];
    const float* bn_gamma     = (const float*)d_in[3];
    const float* bn_beta      = (const float*)d_in[4];
    const float* Wmat         = (const float*)d_in[5];
    const float* bias         = (const float*)d_in[6];
    const int*   docs         = (const int*)d_in[7];
    const int*   edges_matrix = (const int*)d_in[8];
    float* out = (float*)d_out;

    const int smemBytes = (HR * DC * 2 + L_ * WP) * (int)sizeof(float)
                        + L_ * (int)sizeof(int);   // 89,648 B
    cudaFuncSetAttribute(mp_kernel, cudaFuncAttributeMaxDynamicSharedMemorySize, smemBytes);

    edgew_kernel<<<B_, 512>>>(docs, edges_matrix, edge_w, node_eta);

    dim3 grid(NCHUNK, B_);
    mp_kernel<<<grid, 384, smemBytes>>>(node_embed, docs);

    bn_kernel<<<D_, B_>>>(bn_gamma, bn_beta);

    out_kernel<<<B_, 8 * C_>>>(Wmat, bias, out);

    (void)in_sizes; (void)n_in; (void)out_size;
}